// round 12
// baseline (speedup 1.0000x reference)
#include <cuda_runtime.h>
#include <cuda_fp16.h>
#include <math.h>
#include <stdint.h>

#define B_   8
#define N_   2048
#define DIN  256
#define DOUT 128
#define ROWZ 75        // rows [0,75) get attscore = 0
#define TM   64        // queries per block
#define TN   64        // keys per tile (double-buffered)
#define HST  136       // Q/K half-stride (68 words -> bank 4*qr+qc: conflict-free)
#define VST  72        // Vt half-stride   (36 words -> bank 4*qr+qc: conflict-free)

// Scratch (device globals: allocation-free)
__device__ __half g_Whh[B_ * N_ * DOUT];   // 4 MB  Wh fp16 row-major (V source via transpose)
__device__ __half g_Whn[B_ * N_ * DOUT];   // 4 MB  normalized Wh fp16 row-major (Q/K source)
__device__ __half g_WhT[B_ * DOUT * N_];   // 4 MB  Wh^T fp16 [d][n] (Vt source)

__device__ __forceinline__ float to_tf32(float x) {
    unsigned u; asm("cvt.rna.tf32.f32 %0, %1;" : "=r"(u) : "f"(x));
    return __uint_as_float(u);
}
__device__ __forceinline__ void mma_tf32(float d[4], const unsigned a[4], const unsigned b[2]) {
    asm volatile(
        "mma.sync.aligned.m16n8k8.row.col.f32.tf32.tf32.f32 "
        "{%0,%1,%2,%3}, {%4,%5,%6,%7}, {%8,%9}, {%0,%1,%2,%3};\n"
        : "+f"(d[0]), "+f"(d[1]), "+f"(d[2]), "+f"(d[3])
        : "r"(a[0]), "r"(a[1]), "r"(a[2]), "r"(a[3]), "r"(b[0]), "r"(b[1]));
}
__device__ __forceinline__ void mma_f16(float d[4], const unsigned a[4], const unsigned b[2]) {
    asm volatile(
        "mma.sync.aligned.m16n8k16.row.col.f32.f16.f16.f32 "
        "{%0,%1,%2,%3}, {%4,%5,%6,%7}, {%8,%9}, {%0,%1,%2,%3};\n"
        : "+f"(d[0]), "+f"(d[1]), "+f"(d[2]), "+f"(d[3])
        : "r"(a[0]), "r"(a[1]), "r"(a[2]), "r"(a[3]), "r"(b[0]), "r"(b[1]));
}
__device__ __forceinline__ uint32_t cvta_s(const void* p) {
    uint32_t a; asm("{ .reg .u64 t; cvta.to.shared.u64 t, %1; cvt.u32.u64 %0, t; }"
                    : "=r"(a) : "l"(p));
    return a;
}
#define CP_ASYNC16(s, g) \
    asm volatile("cp.async.cg.shared.global [%0], [%1], 16;" :: "r"(s), "l"(g) : "memory")
#define CP_COMMIT() asm volatile("cp.async.commit_group;" ::: "memory")
#define CP_WAIT0()  asm volatile("cp.async.wait_group 0;"  ::: "memory")

// ---------------------------------------------------------------------------
// Phase 1: Wh = h @ W on tf32 MMA, fused row-norm.
// Outputs fp16: Wh (row-major), normalized Wh (row-major), Wh^T.
// ---------------------------------------------------------------------------
__global__ __launch_bounds__(256) void gemmW(const float* __restrict__ h,
                                             const float* __restrict__ W) {
    __shared__ float hs[128 * 36];
    __shared__ float Ws[32 * 132];
    __shared__ float sq[128];

    const int r0  = blockIdx.x * 128;
    const int tid = threadIdx.x;
    const int w   = tid >> 5, lane = tid & 31;
    const int mqw = (w & 3) * 32, dw = (w >> 2) * 64;
    const int qr  = lane >> 2,  qc = lane & 3;

    if (tid < 128) sq[tid] = 0.0f;

    float acc[2][8][4];
#pragma unroll
    for (int mb = 0; mb < 2; mb++)
#pragma unroll
        for (int nb = 0; nb < 8; nb++)
#pragma unroll
            for (int c = 0; c < 4; c++) acc[mb][nb][c] = 0.0f;

    for (int kc = 0; kc < 8; kc++) {
        __syncthreads();
#pragma unroll
        for (int i = tid; i < 128 * 8; i += 256) {
            int r = i >> 3, g = (i & 7) * 4;
            float4 v = *(const float4*)&h[(size_t)(r0 + r) * DIN + kc * 32 + g];
            v.x = to_tf32(v.x); v.y = to_tf32(v.y); v.z = to_tf32(v.z); v.w = to_tf32(v.w);
            *(float4*)&hs[r * 36 + g] = v;
        }
#pragma unroll
        for (int i = tid; i < 32 * 32; i += 256) {
            int r = i >> 5, g = (i & 31) * 4;
            float4 v = *(const float4*)&W[(size_t)(kc * 32 + r) * DOUT + g];
            v.x = to_tf32(v.x); v.y = to_tf32(v.y); v.z = to_tf32(v.z); v.w = to_tf32(v.w);
            *(float4*)&Ws[r * 132 + g] = v;
        }
        __syncthreads();

#pragma unroll
        for (int k0 = 0; k0 < 32; k0 += 8) {
            unsigned a[2][4];
#pragma unroll
            for (int mb = 0; mb < 2; mb++) {
                int base = (mqw + 16 * mb + qr) * 36 + k0 + qc;
                a[mb][0] = *(const unsigned*)&hs[base];
                a[mb][1] = *(const unsigned*)&hs[base + 8 * 36];
                a[mb][2] = *(const unsigned*)&hs[base + 4];
                a[mb][3] = *(const unsigned*)&hs[base + 8 * 36 + 4];
            }
#pragma unroll
            for (int nb = 0; nb < 8; nb++) {
                unsigned bb[2];
                bb[0] = *(const unsigned*)&Ws[(k0 + qc) * 132 + dw + 8 * nb + qr];
                bb[1] = *(const unsigned*)&Ws[(k0 + 4 + qc) * 132 + dw + 8 * nb + qr];
                mma_tf32(acc[0][nb], a[0], bb);
                mma_tf32(acc[1][nb], a[1], bb);
            }
        }
    }

#pragma unroll
    for (int mb = 0; mb < 2; mb++) {
        float s0 = 0.0f, s1 = 0.0f;
#pragma unroll
        for (int nb = 0; nb < 8; nb++) {
            s0 += acc[mb][nb][0] * acc[mb][nb][0] + acc[mb][nb][1] * acc[mb][nb][1];
            s1 += acc[mb][nb][2] * acc[mb][nb][2] + acc[mb][nb][3] * acc[mb][nb][3];
        }
        s0 += __shfl_xor_sync(0xffffffffu, s0, 1); s0 += __shfl_xor_sync(0xffffffffu, s0, 2);
        s1 += __shfl_xor_sync(0xffffffffu, s1, 1); s1 += __shfl_xor_sync(0xffffffffu, s1, 2);
        if (qc == 0) {
            atomicAdd(&sq[mqw + 16 * mb + qr],     s0);
            atomicAdd(&sq[mqw + 16 * mb + 8 + qr], s1);
        }
    }
    __syncthreads();

    const int bb_  = r0 >> 11;
    const int rl0  = r0 & 2047;
    __half* WT = g_WhT + (size_t)bb_ * DOUT * N_;

#pragma unroll
    for (int mb = 0; mb < 2; mb++) {
        int ra = mqw + 16 * mb + qr, rb = ra + 8;
        float inva = 1.0f / fmaxf(sqrtf(sq[ra]), 1e-12f);
        float invb = 1.0f / fmaxf(sqrtf(sq[rb]), 1e-12f);
#pragma unroll
        for (int nb = 0; nb < 8; nb++) {
            int col = dw + 8 * nb + 2 * qc;
            __half2 ha = __floats2half2_rn(acc[mb][nb][0], acc[mb][nb][1]);
            __half2 hb = __floats2half2_rn(acc[mb][nb][2], acc[mb][nb][3]);
            *(__half2*)&g_Whh[(size_t)(r0 + ra) * DOUT + col] = ha;
            *(__half2*)&g_Whh[(size_t)(r0 + rb) * DOUT + col] = hb;
            *(__half2*)&g_Whn[(size_t)(r0 + ra) * DOUT + col] =
                __floats2half2_rn(acc[mb][nb][0] * inva, acc[mb][nb][1] * inva);
            *(__half2*)&g_Whn[(size_t)(r0 + rb) * DOUT + col] =
                __floats2half2_rn(acc[mb][nb][2] * invb, acc[mb][nb][3] * invb);
            WT[(size_t)col       * N_ + rl0 + ra] = __low2half(ha);
            WT[(size_t)(col + 1) * N_ + rl0 + ra] = __high2half(ha);
            WT[(size_t)col       * N_ + rl0 + rb] = __low2half(hb);
            WT[(size_t)(col + 1) * N_ + rl0 + rb] = __high2half(hb);
        }
    }
}

// ---------------------------------------------------------------------------
// Phase 2: fp16 MMA attention, register-resident P, 1 barrier/tile.
// 256 threads. Warps: 4 q-bands(16q) x 2 d-halves. Each warp computes the
// FULL 16q x 64k S (duplicated across halves), keeps P in registers, then
// PV 16q x 64d from register A-fragments. cp.async double-buffered K/Vt.
// ---------------------------------------------------------------------------
__global__ __launch_bounds__(256, 2) void attn(const int* __restrict__ adj,
                                               float* __restrict__ out) {
    extern __shared__ __align__(16) char smraw[];
    __half* Qh  = (__half*)smraw;                 // [64][136]   normalized Q
    __half* Kb  = Qh + TM * HST;                  // 2 x [64][136] normalized K
    __half* Vb  = Kb + 2 * TN * HST;              // 2 x [128][72] Vt (d-major)
    float*  dn  = (float*)(Vb + 2 * DOUT * VST);  // [64]

    const uint32_t sQ = cvta_s(Qh), sK = cvta_s(Kb), sV = cvta_s(Vb);

    const int b     = blockIdx.y;
    const int q0    = blockIdx.x * TM;
    const int tid   = threadIdx.x;
    const int w     = tid >> 5, lane = tid & 31;
    const int band  = w & 3, half = w >> 2;
    const int mqw   = band * 16;
    const int dw    = half * 64;                  // PV d offset
    const int qr    = lane >> 2, qc = lane & 3;

    const __half* WnB  = g_Whn + (size_t)b * N_ * DOUT;
    const __half* WtB  = g_WhT + (size_t)b * DOUT * N_;
    const int*    adjB = adj   + (size_t)b * N_ * N_;

    // prologue group 0: Q tile + K/Vt tile 0
#pragma unroll
    for (int i = tid; i < TM * 16; i += 256) {
        int r = i >> 4, ho = (i & 15) * 8;
        CP_ASYNC16(sQ + (r * HST + ho) * 2, WnB + (size_t)(q0 + r) * DOUT + ho);
        CP_ASYNC16(sK + (r * HST + ho) * 2, WnB + (size_t)r * DOUT + ho);
    }
#pragma unroll
    for (int i = tid; i < DOUT * 8; i += 256) {
        int r = i >> 3, co = (i & 7) * 8;
        CP_ASYNC16(sV + (r * VST + co) * 2, WtB + (size_t)r * N_ + co);
    }
    CP_COMMIT();
    if (tid < TM) dn[tid] = 0.0f;

    bool zq[2];
    zq[0] = (q0 + mqw + qr)     < ROWZ;
    zq[1] = (q0 + mqw + 8 + qr) < ROWZ;
    const int* ap[2];
    ap[0] = adjB + (size_t)(q0 + mqw + qr)     * N_ + 2 * qc;
    ap[1] = adjB + (size_t)(q0 + mqw + 8 + qr) * N_ + 2 * qc;

    float oacc[8][4];
#pragma unroll
    for (int nb = 0; nb < 8; nb++)
#pragma unroll
        for (int c = 0; c < 4; c++) oacc[nb][c] = 0.0f;
    float rsum[2] = {0.f, 0.f};

    for (int it = 0; it < N_ / TN; it++) {
        const int m0  = it * TN;
        const int cur = it & 1;

        CP_WAIT0();          // my tile-it copies done
        __syncthreads();     // all copies visible; prev iter's reads of alt done

        // issue tile it+1 into the alternate buffer (hidden under this tile)
        if (it < N_ / TN - 1) {
            const int mn = m0 + TN, alt = cur ^ 1;
#pragma unroll
            for (int i = tid; i < TN * 16; i += 256) {
                int r = i >> 4, ho = (i & 15) * 8;
                CP_ASYNC16(sK + (alt * TN * HST + r * HST + ho) * 2,
                           WnB + (size_t)(mn + r) * DOUT + ho);
            }
#pragma unroll
            for (int i = tid; i < DOUT * 8; i += 256) {
                int r = i >> 3, co = (i & 7) * 8;
                CP_ASYNC16(sV + (alt * DOUT * VST + r * VST + co) * 2,
                           WtB + (size_t)r * N_ + mn + co);
            }
        }
        CP_COMMIT();

        // adjacency masks (consumed after S — latency shadowed)
        // bit = rp*16 + nb*2 + c
        unsigned msk = 0;
#pragma unroll
        for (int rp = 0; rp < 2; rp++)
#pragma unroll
            for (int nb = 0; nb < 8; nb++) {
                int2 v = *(const int2*)(ap[rp] + m0 + 8 * nb);
                msk |= (unsigned)(v.x > 0) << (rp * 16 + nb * 2);
                msk |= (unsigned)(v.y > 0) << (rp * 16 + nb * 2 + 1);
            }

        // ---- S = Qn.Kn^T  (warp: 16q x 64k, cosine scores) ----
        const __half* Kc = Kb + cur * TN * HST;
        float sacc[8][4];
#pragma unroll
        for (int nb = 0; nb < 8; nb++)
#pragma unroll
            for (int c = 0; c < 4; c++) sacc[nb][c] = 0.0f;

#pragma unroll
        for (int k0 = 0; k0 < DOUT; k0 += 16) {
            unsigned a[4];
            int base = (mqw + qr) * HST + k0 + 2 * qc;
            a[0] = *(const unsigned*)&Qh[base];
            a[1] = *(const unsigned*)&Qh[base + 8 * HST];
            a[2] = *(const unsigned*)&Qh[base + 8];
            a[3] = *(const unsigned*)&Qh[base + 8 * HST + 8];
#pragma unroll
            for (int nb = 0; nb < 8; nb++) {
                int bbase = (8 * nb + qr) * HST + k0 + 2 * qc;
                unsigned bb[2];
                bb[0] = *(const unsigned*)&Kc[bbase];
                bb[1] = *(const unsigned*)&Kc[bbase + 8];
                mma_f16(sacc[nb], a, bb);
            }
        }

        // ---- mask + exp -> P packed in registers ----
        unsigned pfrag[8][2];
#pragma unroll
        for (int nb = 0; nb < 8; nb++) {
            unsigned ml = msk >> (nb * 2);
            unsigned mh = msk >> (16 + nb * 2);
            float p0 = (ml & 1u) ? __expf(zq[0] ? 0.f : sacc[nb][0]) : 0.f;
            float p1 = (ml & 2u) ? __expf(zq[0] ? 0.f : sacc[nb][1]) : 0.f;
            float p2 = (mh & 1u) ? __expf(zq[1] ? 0.f : sacc[nb][2]) : 0.f;
            float p3 = (mh & 2u) ? __expf(zq[1] ? 0.f : sacc[nb][3]) : 0.f;
            __half2 ha = __floats2half2_rn(p0, p1);
            __half2 hb = __floats2half2_rn(p2, p3);
            float2 fa = __half22float2(ha), fb = __half22float2(hb);
            rsum[0] += fa.x + fa.y;
            rsum[1] += fb.x + fb.y;
            pfrag[nb][0] = *(unsigned*)&ha;
            pfrag[nb][1] = *(unsigned*)&hb;
        }

        // ---- O += P.V  (warp: 16q x 64d, A from registers, B = Vt) ----
        const __half* Vc = Vb + cur * DOUT * VST;
#pragma unroll
        for (int kc = 0; kc < 4; kc++) {
            unsigned a[4];
            a[0] = pfrag[2 * kc][0];
            a[1] = pfrag[2 * kc][1];
            a[2] = pfrag[2 * kc + 1][0];
            a[3] = pfrag[2 * kc + 1][1];
#pragma unroll
            for (int nb = 0; nb < 8; nb++) {
                int bbase = (dw + 8 * nb + qr) * VST + kc * 16 + 2 * qc;
                unsigned bb[2];
                bb[0] = *(const unsigned*)&Vc[bbase];
                bb[1] = *(const unsigned*)&Vc[bbase + 8];
                mma_f16(oacc[nb], a, bb);
            }
        }
    }

    // denominators (halves compute identical sums: only half 0 contributes)
#pragma unroll
    for (int rp = 0; rp < 2; rp++) {
        float v = rsum[rp];
        v += __shfl_xor_sync(0xffffffffu, v, 1);
        v += __shfl_xor_sync(0xffffffffu, v, 2);
        if (half == 0 && qc == 0) atomicAdd(&dn[mqw + 8 * rp + qr], v);
    }
    __syncthreads();

    // epilogue: divide, ELU, store (warp: 16q x 64d)
    {
        float i0 = 1.0f / fmaxf(dn[mqw + qr],     1e-30f);
        float i1 = 1.0f / fmaxf(dn[mqw + 8 + qr], 1e-30f);
        int r0 = q0 + mqw + qr;
#pragma unroll
        for (int nb = 0; nb < 8; nb++) {
            int col = dw + 8 * nb + 2 * qc;
            float v0 = oacc[nb][0] * i0, v1 = oacc[nb][1] * i0;
            float v2 = oacc[nb][2] * i1, v3 = oacc[nb][3] * i1;
            v0 = (v0 > 0.f) ? v0 : expm1f(v0);
            v1 = (v1 > 0.f) ? v1 : expm1f(v1);
            v2 = (v2 > 0.f) ? v2 : expm1f(v2);
            v3 = (v3 > 0.f) ? v3 : expm1f(v3);
            *(float2*)&out[((size_t)b * N_ + r0)     * DOUT + col] = make_float2(v0, v1);
            *(float2*)&out[((size_t)b * N_ + r0 + 8) * DOUT + col] = make_float2(v2, v3);
        }
    }
}

// ---------------------------------------------------------------------------
// Launch
// ---------------------------------------------------------------------------
extern "C" void kernel_launch(void* const* d_in, const int* in_sizes, int n_in,
                              void* d_out, int out_size) {
    const float* h       = (const float*)d_in[0];   // [8,2048,256] f32
    // d_in[1] = adj (unused by the reference math)
    const int*   adj_eye = (const int*)d_in[2];     // [8,2048,2048] i32
    const float* W       = (const float*)d_in[3];   // [256,128] f32
    float* out = (float*)d_out;                     // [8,2048,128] f32

    const int smem_bytes =
        (TM * HST + 2 * TN * HST + 2 * DOUT * VST) * 2 + TM * 4;   // 89,344 B
    cudaFuncSetAttribute(attn, cudaFuncAttributeMaxDynamicSharedMemorySize, smem_bytes);

    gemmW<<<(B_ * N_) / 128, 256>>>(h, W);
    attn<<<dim3(N_ / TM, B_), 256, smem_bytes>>>(adj_eye, out);
}

// round 13
// speedup vs baseline: 1.6162x; 1.6162x over previous
#include <cuda_runtime.h>
#include <cuda_fp16.h>
#include <math.h>
#include <stdint.h>

#define B_   8
#define N_   2048
#define DIN  256
#define DOUT 128
#define ROWZ 75        // rows [0,75) get attscore = 0
#define TM   64        // queries per block
#define TN   64        // keys per tile (double-buffered)
#define HST  136       // Q/K half-stride (68 words -> bank 4*qr+qc: conflict-free)
#define VST  72        // Vt half-stride   (36 words -> bank 4*qr+qc: conflict-free)

// Scratch (device globals: allocation-free)
__device__ __half g_Whn[B_ * N_ * DOUT];   // 4 MB  normalized Wh fp16 row-major (Q/K source)
__device__ __half g_WhT[B_ * DOUT * N_];   // 4 MB  Wh^T fp16 [d][n] (Vt source, unnormalized)

__device__ __forceinline__ float to_tf32(float x) {
    unsigned u; asm("cvt.rna.tf32.f32 %0, %1;" : "=r"(u) : "f"(x));
    return __uint_as_float(u);
}
__device__ __forceinline__ void mma_tf32(float d[4], const unsigned a[4], const unsigned b[2]) {
    asm volatile(
        "mma.sync.aligned.m16n8k8.row.col.f32.tf32.tf32.f32 "
        "{%0,%1,%2,%3}, {%4,%5,%6,%7}, {%8,%9}, {%0,%1,%2,%3};\n"
        : "+f"(d[0]), "+f"(d[1]), "+f"(d[2]), "+f"(d[3])
        : "r"(a[0]), "r"(a[1]), "r"(a[2]), "r"(a[3]), "r"(b[0]), "r"(b[1]));
}
__device__ __forceinline__ void mma_f16(float d[4], const unsigned a[4], const unsigned b[2]) {
    asm volatile(
        "mma.sync.aligned.m16n8k16.row.col.f32.f16.f16.f32 "
        "{%0,%1,%2,%3}, {%4,%5,%6,%7}, {%8,%9}, {%0,%1,%2,%3};\n"
        : "+f"(d[0]), "+f"(d[1]), "+f"(d[2]), "+f"(d[3])
        : "r"(a[0]), "r"(a[1]), "r"(a[2]), "r"(a[3]), "r"(b[0]), "r"(b[1]));
}
__device__ __forceinline__ uint32_t cvta_s(const void* p) {
    uint32_t a; asm("{ .reg .u64 t; cvta.to.shared.u64 t, %1; cvt.u32.u64 %0, t; }"
                    : "=r"(a) : "l"(p));
    return a;
}
#define CP_ASYNC16(s, g) \
    asm volatile("cp.async.cg.shared.global [%0], [%1], 16;" :: "r"(s), "l"(g) : "memory")
#define CP_COMMIT() asm volatile("cp.async.commit_group;" ::: "memory")
#define CP_WAIT0()  asm volatile("cp.async.wait_group 0;"  ::: "memory")

// ---------------------------------------------------------------------------
// Phase 1: Wh = h @ W on tf32 MMA, fused row-norm.
// Outputs fp16: normalized Wh (row-major, Q/K) and Wh^T (unnormalized, V).
// ---------------------------------------------------------------------------
__global__ __launch_bounds__(256) void gemmW(const float* __restrict__ h,
                                             const float* __restrict__ W) {
    __shared__ float hs[128 * 36];
    __shared__ float Ws[32 * 132];
    __shared__ float sq[128];

    const int r0  = blockIdx.x * 128;
    const int tid = threadIdx.x;
    const int w   = tid >> 5, lane = tid & 31;
    const int mqw = (w & 3) * 32, dw = (w >> 2) * 64;
    const int qr  = lane >> 2,  qc = lane & 3;

    if (tid < 128) sq[tid] = 0.0f;

    float acc[2][8][4];
#pragma unroll
    for (int mb = 0; mb < 2; mb++)
#pragma unroll
        for (int nb = 0; nb < 8; nb++)
#pragma unroll
            for (int c = 0; c < 4; c++) acc[mb][nb][c] = 0.0f;

    for (int kc = 0; kc < 8; kc++) {
        __syncthreads();
#pragma unroll
        for (int i = tid; i < 128 * 8; i += 256) {
            int r = i >> 3, g = (i & 7) * 4;
            float4 v = *(const float4*)&h[(size_t)(r0 + r) * DIN + kc * 32 + g];
            v.x = to_tf32(v.x); v.y = to_tf32(v.y); v.z = to_tf32(v.z); v.w = to_tf32(v.w);
            *(float4*)&hs[r * 36 + g] = v;
        }
#pragma unroll
        for (int i = tid; i < 32 * 32; i += 256) {
            int r = i >> 5, g = (i & 31) * 4;
            float4 v = *(const float4*)&W[(size_t)(kc * 32 + r) * DOUT + g];
            v.x = to_tf32(v.x); v.y = to_tf32(v.y); v.z = to_tf32(v.z); v.w = to_tf32(v.w);
            *(float4*)&Ws[r * 132 + g] = v;
        }
        __syncthreads();

#pragma unroll
        for (int k0 = 0; k0 < 32; k0 += 8) {
            unsigned a[2][4];
#pragma unroll
            for (int mb = 0; mb < 2; mb++) {
                int base = (mqw + 16 * mb + qr) * 36 + k0 + qc;
                a[mb][0] = *(const unsigned*)&hs[base];
                a[mb][1] = *(const unsigned*)&hs[base + 8 * 36];
                a[mb][2] = *(const unsigned*)&hs[base + 4];
                a[mb][3] = *(const unsigned*)&hs[base + 8 * 36 + 4];
            }
#pragma unroll
            for (int nb = 0; nb < 8; nb++) {
                unsigned bb[2];
                bb[0] = *(const unsigned*)&Ws[(k0 + qc) * 132 + dw + 8 * nb + qr];
                bb[1] = *(const unsigned*)&Ws[(k0 + 4 + qc) * 132 + dw + 8 * nb + qr];
                mma_tf32(acc[0][nb], a[0], bb);
                mma_tf32(acc[1][nb], a[1], bb);
            }
        }
    }

#pragma unroll
    for (int mb = 0; mb < 2; mb++) {
        float s0 = 0.0f, s1 = 0.0f;
#pragma unroll
        for (int nb = 0; nb < 8; nb++) {
            s0 += acc[mb][nb][0] * acc[mb][nb][0] + acc[mb][nb][1] * acc[mb][nb][1];
            s1 += acc[mb][nb][2] * acc[mb][nb][2] + acc[mb][nb][3] * acc[mb][nb][3];
        }
        s0 += __shfl_xor_sync(0xffffffffu, s0, 1); s0 += __shfl_xor_sync(0xffffffffu, s0, 2);
        s1 += __shfl_xor_sync(0xffffffffu, s1, 1); s1 += __shfl_xor_sync(0xffffffffu, s1, 2);
        if (qc == 0) {
            atomicAdd(&sq[mqw + 16 * mb + qr],     s0);
            atomicAdd(&sq[mqw + 16 * mb + 8 + qr], s1);
        }
    }
    __syncthreads();

    const int bb_  = r0 >> 11;
    const int rl0  = r0 & 2047;
    __half* WT = g_WhT + (size_t)bb_ * DOUT * N_;

#pragma unroll
    for (int mb = 0; mb < 2; mb++) {
        int ra = mqw + 16 * mb + qr, rb = ra + 8;
        float inva = 1.0f / fmaxf(sqrtf(sq[ra]), 1e-12f);
        float invb = 1.0f / fmaxf(sqrtf(sq[rb]), 1e-12f);
#pragma unroll
        for (int nb = 0; nb < 8; nb++) {
            int col = dw + 8 * nb + 2 * qc;
            __half2 ha = __floats2half2_rn(acc[mb][nb][0], acc[mb][nb][1]);
            __half2 hb = __floats2half2_rn(acc[mb][nb][2], acc[mb][nb][3]);
            *(__half2*)&g_Whn[(size_t)(r0 + ra) * DOUT + col] =
                __floats2half2_rn(acc[mb][nb][0] * inva, acc[mb][nb][1] * inva);
            *(__half2*)&g_Whn[(size_t)(r0 + rb) * DOUT + col] =
                __floats2half2_rn(acc[mb][nb][2] * invb, acc[mb][nb][3] * invb);
            WT[(size_t)col       * N_ + rl0 + ra] = __low2half(ha);
            WT[(size_t)(col + 1) * N_ + rl0 + ra] = __high2half(ha);
            WT[(size_t)col       * N_ + rl0 + rb] = __low2half(hb);
            WT[(size_t)(col + 1) * N_ + rl0 + rb] = __high2half(hb);
        }
    }
}

// ---------------------------------------------------------------------------
// Phase 2: fp16 MMA attention, split-K partial-O, register P, 1 barrier/tile.
// 256 threads. Warps: 4 q-bands(16q) x 2 key-splits(32k). Each warp: S for its
// own 32 keys, P in registers, partial O over its keys for ALL 128 d.
// Cross-split O combine once at epilogue. cp.async double-buffered K/Vt.
// ---------------------------------------------------------------------------
__global__ __launch_bounds__(256, 2) void attn(const int* __restrict__ adj,
                                               float* __restrict__ out) {
    extern __shared__ __align__(16) char smraw[];
    __half* Qh  = (__half*)smraw;                 // [64][136]   normalized Q
    __half* Kb  = Qh + TM * HST;                  // 2 x [64][136] normalized K
    __half* Vb  = Kb + 2 * TN * HST;              // 2 x [128][72] Vt (d-major)
    float*  dn  = (float*)(Vb + 2 * DOUT * VST);  // [64]
    float*  Ox  = (float*)Kb;                     // epilogue overlay: [64][132]

    const uint32_t sQ = cvta_s(Qh), sK = cvta_s(Kb), sV = cvta_s(Vb);

    const int b     = blockIdx.y;
    const int q0    = blockIdx.x * TM;
    const int tid   = threadIdx.x;
    const int w     = tid >> 5, lane = tid & 31;
    const int band  = w & 3, split = w >> 2;
    const int mqw   = band * 16;
    const int nkw   = split * 32;                 // this warp's key sub-range
    const int qr    = lane >> 2, qc = lane & 3;

    const __half* WnB  = g_Whn + (size_t)b * N_ * DOUT;
    const __half* WtB  = g_WhT + (size_t)b * DOUT * N_;
    const int*    adjB = adj   + (size_t)b * N_ * N_;

    // prologue group 0: Q tile + K/Vt tile 0
#pragma unroll
    for (int i = tid; i < TM * 16; i += 256) {
        int r = i >> 4, ho = (i & 15) * 8;
        CP_ASYNC16(sQ + (r * HST + ho) * 2, WnB + (size_t)(q0 + r) * DOUT + ho);
        CP_ASYNC16(sK + (r * HST + ho) * 2, WnB + (size_t)r * DOUT + ho);
    }
#pragma unroll
    for (int i = tid; i < DOUT * 8; i += 256) {
        int r = i >> 3, co = (i & 7) * 8;
        CP_ASYNC16(sV + (r * VST + co) * 2, WtB + (size_t)r * N_ + co);
    }
    CP_COMMIT();
    if (tid < TM) dn[tid] = 0.0f;

    bool zq[2];
    zq[0] = (q0 + mqw + qr)     < ROWZ;
    zq[1] = (q0 + mqw + 8 + qr) < ROWZ;
    const int* ap[2];
    ap[0] = adjB + (size_t)(q0 + mqw + qr)     * N_ + nkw + 2 * qc;
    ap[1] = adjB + (size_t)(q0 + mqw + 8 + qr) * N_ + nkw + 2 * qc;

    float oacc[16][4];   // partial O: 16q x 128d over this warp's keys
#pragma unroll
    for (int nb = 0; nb < 16; nb++)
#pragma unroll
        for (int c = 0; c < 4; c++) oacc[nb][c] = 0.0f;
    float rsum[2] = {0.f, 0.f};

    for (int it = 0; it < N_ / TN; it++) {
        const int m0  = it * TN;
        const int cur = it & 1;

        CP_WAIT0();          // my tile-it copies done
        __syncthreads();     // all copies visible; prev iter's reads of alt done

        // issue tile it+1 into the alternate buffer (hidden under this tile)
        if (it < N_ / TN - 1) {
            const int mn = m0 + TN, alt = cur ^ 1;
#pragma unroll
            for (int i = tid; i < TN * 16; i += 256) {
                int r = i >> 4, ho = (i & 15) * 8;
                CP_ASYNC16(sK + (alt * TN * HST + r * HST + ho) * 2,
                           WnB + (size_t)(mn + r) * DOUT + ho);
            }
#pragma unroll
            for (int i = tid; i < DOUT * 8; i += 256) {
                int r = i >> 3, co = (i & 7) * 8;
                CP_ASYNC16(sV + (alt * DOUT * VST + r * VST + co) * 2,
                           WtB + (size_t)r * N_ + mn + co);
            }
        }
        CP_COMMIT();

        // adjacency masks for this warp's 32 keys (consumed after S)
        unsigned msk = 0;
#pragma unroll
        for (int rp = 0; rp < 2; rp++)
#pragma unroll
            for (int nb = 0; nb < 4; nb++) {
                int2 v = *(const int2*)(ap[rp] + m0 + 8 * nb);
                msk |= (unsigned)(v.x > 0) << (rp * 8 + nb * 2);
                msk |= (unsigned)(v.y > 0) << (rp * 8 + nb * 2 + 1);
            }

        // ---- S = Qn.Kn^T  (warp: 16q x 32k, own keys) ----
        const __half* Kc = Kb + cur * TN * HST;
        float sacc[4][4];
#pragma unroll
        for (int nb = 0; nb < 4; nb++)
#pragma unroll
            for (int c = 0; c < 4; c++) sacc[nb][c] = 0.0f;

#pragma unroll
        for (int k0 = 0; k0 < DOUT; k0 += 16) {
            unsigned a[4];
            int base = (mqw + qr) * HST + k0 + 2 * qc;
            a[0] = *(const unsigned*)&Qh[base];
            a[1] = *(const unsigned*)&Qh[base + 8 * HST];
            a[2] = *(const unsigned*)&Qh[base + 8];
            a[3] = *(const unsigned*)&Qh[base + 8 * HST + 8];
#pragma unroll
            for (int nb = 0; nb < 4; nb++) {
                int bbase = (nkw + 8 * nb + qr) * HST + k0 + 2 * qc;
                unsigned bb[2];
                bb[0] = *(const unsigned*)&Kc[bbase];
                bb[1] = *(const unsigned*)&Kc[bbase + 8];
                mma_f16(sacc[nb], a, bb);
            }
        }

        // ---- mask + exp -> P packed in registers ----
        unsigned pfrag[4][2];
#pragma unroll
        for (int nb = 0; nb < 4; nb++) {
            unsigned ml = msk >> (nb * 2);
            unsigned mh = msk >> (8 + nb * 2);
            float p0 = (ml & 1u) ? __expf(zq[0] ? 0.f : sacc[nb][0]) : 0.f;
            float p1 = (ml & 2u) ? __expf(zq[0] ? 0.f : sacc[nb][1]) : 0.f;
            float p2 = (mh & 1u) ? __expf(zq[1] ? 0.f : sacc[nb][2]) : 0.f;
            float p3 = (mh & 2u) ? __expf(zq[1] ? 0.f : sacc[nb][3]) : 0.f;
            __half2 ha = __floats2half2_rn(p0, p1);
            __half2 hb = __floats2half2_rn(p2, p3);
            float2 fa = __half22float2(ha), fb = __half22float2(hb);
            rsum[0] += fa.x + fa.y;
            rsum[1] += fb.x + fb.y;
            pfrag[nb][0] = *(unsigned*)&ha;
            pfrag[nb][1] = *(unsigned*)&hb;
        }

        // ---- partial O += P.V (own 32 keys, all 128 d; A from registers) ----
        const __half* Vc = Vb + cur * DOUT * VST;
#pragma unroll
        for (int kc = 0; kc < 2; kc++) {
            unsigned a[4];
            a[0] = pfrag[2 * kc][0];
            a[1] = pfrag[2 * kc][1];
            a[2] = pfrag[2 * kc + 1][0];
            a[3] = pfrag[2 * kc + 1][1];
#pragma unroll
            for (int nb = 0; nb < 16; nb++) {
                int bbase = (8 * nb + qr) * VST + nkw + kc * 16 + 2 * qc;
                unsigned bb[2];
                bb[0] = *(const unsigned*)&Vc[bbase];
                bb[1] = *(const unsigned*)&Vc[bbase + 8];
                mma_f16(oacc[nb], a, bb);
            }
        }
    }

    // denominators (each split adds its own keys' sums)
#pragma unroll
    for (int rp = 0; rp < 2; rp++) {
        float v = rsum[rp];
        v += __shfl_xor_sync(0xffffffffu, v, 1);
        v += __shfl_xor_sync(0xffffffffu, v, 2);
        if (qc == 0) atomicAdd(&dn[mqw + 8 * rp + qr], v);
    }
    __syncthreads();   // dn complete; K/V buffers dead -> Ox overlay safe

    // cross-split O combine: split 1 parks its partial in smem
    if (split == 1) {
#pragma unroll
        for (int nb = 0; nb < 16; nb++) {
            int col = 8 * nb + 2 * qc;
            *(float2*)&Ox[(mqw + qr)     * 132 + col] = make_float2(oacc[nb][0], oacc[nb][1]);
            *(float2*)&Ox[(mqw + 8 + qr) * 132 + col] = make_float2(oacc[nb][2], oacc[nb][3]);
        }
    }
    __syncthreads();

    // split 0: combine, divide, ELU, store all 128 d
    if (split == 0) {
        float i0 = 1.0f / fmaxf(dn[mqw + qr],     1e-30f);
        float i1 = 1.0f / fmaxf(dn[mqw + 8 + qr], 1e-30f);
        int r0 = q0 + mqw + qr;
#pragma unroll
        for (int nb = 0; nb < 16; nb++) {
            int col = 8 * nb + 2 * qc;
            float2 xa = *(const float2*)&Ox[(mqw + qr)     * 132 + col];
            float2 xb = *(const float2*)&Ox[(mqw + 8 + qr) * 132 + col];
            float v0 = (oacc[nb][0] + xa.x) * i0, v1 = (oacc[nb][1] + xa.y) * i0;
            float v2 = (oacc[nb][2] + xb.x) * i1, v3 = (oacc[nb][3] + xb.y) * i1;
            v0 = (v0 > 0.f) ? v0 : expm1f(v0);
            v1 = (v1 > 0.f) ? v1 : expm1f(v1);
            v2 = (v2 > 0.f) ? v2 : expm1f(v2);
            v3 = (v3 > 0.f) ? v3 : expm1f(v3);
            *(float2*)&out[((size_t)b * N_ + r0)     * DOUT + col] = make_float2(v0, v1);
            *(float2*)&out[((size_t)b * N_ + r0 + 8) * DOUT + col] = make_float2(v2, v3);
        }
    }
}

// ---------------------------------------------------------------------------
// Launch
// ---------------------------------------------------------------------------
extern "C" void kernel_launch(void* const* d_in, const int* in_sizes, int n_in,
                              void* d_out, int out_size) {
    const float* h       = (const float*)d_in[0];   // [8,2048,256] f32
    // d_in[1] = adj (unused by the reference math)
    const int*   adj_eye = (const int*)d_in[2];     // [8,2048,2048] i32
    const float* W       = (const float*)d_in[3];   // [256,128] f32
    float* out = (float*)d_out;                     // [8,2048,128] f32

    const int smem_bytes =
        (TM * HST + 2 * TN * HST + 2 * DOUT * VST) * 2 + TM * 4;   // 89,344 B
    cudaFuncSetAttribute(attn, cudaFuncAttributeMaxDynamicSharedMemorySize, smem_bytes);

    gemmW<<<(B_ * N_) / 128, 256>>>(h, W);
    attn<<<dim3(N_ / TM, B_), 256, smem_bytes>>>(adj_eye, out);
}

// round 16
// speedup vs baseline: 1.7181x; 1.0630x over previous
#include <cuda_runtime.h>
#include <cuda_fp16.h>
#include <math.h>
#include <stdint.h>

#define B_   8
#define N_   2048
#define DIN  256
#define DOUT 128
#define ROWZ 75        // rows [0,75) get attscore = 0
#define TM   64        // queries per block
#define TN   64        // keys per tile (double-buffered)
#define HST  136       // Q/K half-stride (rows -> banks 4i: LDSM conflict-free)
#define VST  72        // Vt half-stride  (rows -> banks 4i: LDSM conflict-free)

// Scratch (device globals: allocation-free)
__device__ __half g_Whn[B_ * N_ * DOUT];   // 4 MB  normalized Wh fp16 row-major (Q/K source)
__device__ __half g_WhT[B_ * DOUT * N_];   // 4 MB  Wh^T fp16 [d][n] (Vt source, unnormalized)

__device__ __forceinline__ float to_tf32(float x) {
    unsigned u; asm("cvt.rna.tf32.f32 %0, %1;" : "=r"(u) : "f"(x));
    return __uint_as_float(u);
}
__device__ __forceinline__ void mma_tf32(float d[4], const unsigned a[4], const unsigned b[2]) {
    asm volatile(
        "mma.sync.aligned.m16n8k8.row.col.f32.tf32.tf32.f32 "
        "{%0,%1,%2,%3}, {%4,%5,%6,%7}, {%8,%9}, {%0,%1,%2,%3};\n"
        : "+f"(d[0]), "+f"(d[1]), "+f"(d[2]), "+f"(d[3])
        : "r"(a[0]), "r"(a[1]), "r"(a[2]), "r"(a[3]), "r"(b[0]), "r"(b[1]));
}
__device__ __forceinline__ void mma_f16(float d[4], const unsigned a[4], const unsigned b0, const unsigned b1) {
    asm volatile(
        "mma.sync.aligned.m16n8k16.row.col.f32.f16.f16.f32 "
        "{%0,%1,%2,%3}, {%4,%5,%6,%7}, {%8,%9}, {%0,%1,%2,%3};\n"
        : "+f"(d[0]), "+f"(d[1]), "+f"(d[2]), "+f"(d[3])
        : "r"(a[0]), "r"(a[1]), "r"(a[2]), "r"(a[3]), "r"(b0), "r"(b1));
}
__device__ __forceinline__ void ldsm_x4(unsigned& r0, unsigned& r1, unsigned& r2, unsigned& r3,
                                        uint32_t addr) {
    asm volatile("ldmatrix.sync.aligned.m8n8.x4.shared.b16 {%0,%1,%2,%3}, [%4];"
                 : "=r"(r0), "=r"(r1), "=r"(r2), "=r"(r3) : "r"(addr));
}
__device__ __forceinline__ uint32_t cvta_s(const void* p) {
    uint32_t a; asm("{ .reg .u64 t; cvta.to.shared.u64 t, %1; cvt.u32.u64 %0, t; }"
                    : "=r"(a) : "l"(p));
    return a;
}
#define CP_ASYNC16(s, g) \
    asm volatile("cp.async.cg.shared.global [%0], [%1], 16;" :: "r"(s), "l"(g) : "memory")
#define CP_COMMIT() asm volatile("cp.async.commit_group;" ::: "memory")
#define CP_WAIT0()  asm volatile("cp.async.wait_group 0;"  ::: "memory")

// ---------------------------------------------------------------------------
// Phase 1: Wh = h @ W on tf32 MMA, fused row-norm. (unchanged — passing)
// Outputs fp16: normalized Wh (row-major, Q/K) and Wh^T (unnormalized, V).
// ---------------------------------------------------------------------------
__global__ __launch_bounds__(256) void gemmW(const float* __restrict__ h,
                                             const float* __restrict__ W) {
    __shared__ float hs[128 * 36];
    __shared__ float Ws[32 * 132];
    __shared__ float sq[128];

    const int r0  = blockIdx.x * 128;
    const int tid = threadIdx.x;
    const int w   = tid >> 5, lane = tid & 31;
    const int mqw = (w & 3) * 32, dw = (w >> 2) * 64;
    const int qr  = lane >> 2,  qc = lane & 3;

    if (tid < 128) sq[tid] = 0.0f;

    float acc[2][8][4];
#pragma unroll
    for (int mb = 0; mb < 2; mb++)
#pragma unroll
        for (int nb = 0; nb < 8; nb++)
#pragma unroll
            for (int c = 0; c < 4; c++) acc[mb][nb][c] = 0.0f;

    for (int kc = 0; kc < 8; kc++) {
        __syncthreads();
#pragma unroll
        for (int i = tid; i < 128 * 8; i += 256) {
            int r = i >> 3, g = (i & 7) * 4;
            float4 v = *(const float4*)&h[(size_t)(r0 + r) * DIN + kc * 32 + g];
            v.x = to_tf32(v.x); v.y = to_tf32(v.y); v.z = to_tf32(v.z); v.w = to_tf32(v.w);
            *(float4*)&hs[r * 36 + g] = v;
        }
#pragma unroll
        for (int i = tid; i < 32 * 32; i += 256) {
            int r = i >> 5, g = (i & 31) * 4;
            float4 v = *(const float4*)&W[(size_t)(kc * 32 + r) * DOUT + g];
            v.x = to_tf32(v.x); v.y = to_tf32(v.y); v.z = to_tf32(v.z); v.w = to_tf32(v.w);
            *(float4*)&Ws[r * 132 + g] = v;
        }
        __syncthreads();

#pragma unroll
        for (int k0 = 0; k0 < 32; k0 += 8) {
            unsigned a[2][4];
#pragma unroll
            for (int mb = 0; mb < 2; mb++) {
                int base = (mqw + 16 * mb + qr) * 36 + k0 + qc;
                a[mb][0] = *(const unsigned*)&hs[base];
                a[mb][1] = *(const unsigned*)&hs[base + 8 * 36];
                a[mb][2] = *(const unsigned*)&hs[base + 4];
                a[mb][3] = *(const unsigned*)&hs[base + 8 * 36 + 4];
            }
#pragma unroll
            for (int nb = 0; nb < 8; nb++) {
                unsigned bb[2];
                bb[0] = *(const unsigned*)&Ws[(k0 + qc) * 132 + dw + 8 * nb + qr];
                bb[1] = *(const unsigned*)&Ws[(k0 + 4 + qc) * 132 + dw + 8 * nb + qr];
                mma_tf32(acc[0][nb], a[0], bb);
                mma_tf32(acc[1][nb], a[1], bb);
            }
        }
    }

#pragma unroll
    for (int mb = 0; mb < 2; mb++) {
        float s0 = 0.0f, s1 = 0.0f;
#pragma unroll
        for (int nb = 0; nb < 8; nb++) {
            s0 += acc[mb][nb][0] * acc[mb][nb][0] + acc[mb][nb][1] * acc[mb][nb][1];
            s1 += acc[mb][nb][2] * acc[mb][nb][2] + acc[mb][nb][3] * acc[mb][nb][3];
        }
        s0 += __shfl_xor_sync(0xffffffffu, s0, 1); s0 += __shfl_xor_sync(0xffffffffu, s0, 2);
        s1 += __shfl_xor_sync(0xffffffffu, s1, 1); s1 += __shfl_xor_sync(0xffffffffu, s1, 2);
        if (qc == 0) {
            atomicAdd(&sq[mqw + 16 * mb + qr],     s0);
            atomicAdd(&sq[mqw + 16 * mb + 8 + qr], s1);
        }
    }
    __syncthreads();

    const int bb_  = r0 >> 11;
    const int rl0  = r0 & 2047;
    __half* WT = g_WhT + (size_t)bb_ * DOUT * N_;

#pragma unroll
    for (int mb = 0; mb < 2; mb++) {
        int ra = mqw + 16 * mb + qr, rb = ra + 8;
        float inva = 1.0f / fmaxf(sqrtf(sq[ra]), 1e-12f);
        float invb = 1.0f / fmaxf(sqrtf(sq[rb]), 1e-12f);
#pragma unroll
        for (int nb = 0; nb < 8; nb++) {
            int col = dw + 8 * nb + 2 * qc;
            __half2 ha = __floats2half2_rn(acc[mb][nb][0], acc[mb][nb][1]);
            __half2 hb = __floats2half2_rn(acc[mb][nb][2], acc[mb][nb][3]);
            *(__half2*)&g_Whn[(size_t)(r0 + ra) * DOUT + col] =
                __floats2half2_rn(acc[mb][nb][0] * inva, acc[mb][nb][1] * inva);
            *(__half2*)&g_Whn[(size_t)(r0 + rb) * DOUT + col] =
                __floats2half2_rn(acc[mb][nb][2] * invb, acc[mb][nb][3] * invb);
            WT[(size_t)col       * N_ + rl0 + ra] = __low2half(ha);
            WT[(size_t)(col + 1) * N_ + rl0 + ra] = __high2half(ha);
            WT[(size_t)col       * N_ + rl0 + rb] = __low2half(hb);
            WT[(size_t)(col + 1) * N_ + rl0 + rb] = __high2half(hb);
        }
    }
}

// ---------------------------------------------------------------------------
// Phase 2: fp16 MMA attention, ldmatrix fragment feed, split-K partial-O,
// register P, 1 barrier/tile. 256 threads: 4 q-bands(16q) x 2 key-splits(32k).
// ---------------------------------------------------------------------------
__global__ __launch_bounds__(256, 2) void attn(const int* __restrict__ adj,
                                               float* __restrict__ out) {
    extern __shared__ __align__(16) char smraw[];
    __half* Qh  = (__half*)smraw;                 // [64][136]   normalized Q
    __half* Kb  = Qh + TM * HST;                  // 2 x [64][136] normalized K
    __half* Vb  = Kb + 2 * TN * HST;              // 2 x [128][72] Vt (d-major)
    float*  dn  = (float*)(Vb + 2 * DOUT * VST);  // [64]
    float*  Ox  = (float*)Kb;                     // epilogue overlay: [64][132]

    const uint32_t sQ = cvta_s(Qh), sK = cvta_s(Kb), sV = cvta_s(Vb);

    const int b     = blockIdx.y;
    const int q0    = blockIdx.x * TM;
    const int tid   = threadIdx.x;
    const int w     = tid >> 5, lane = tid & 31;
    const int band  = w & 3, split = w >> 2;
    const int mqw   = band * 16;
    const int nkw   = split * 32;                 // this warp's key sub-range
    const int qr    = lane >> 2, qc = lane & 3;

    // ldmatrix lane geometry (m8n8.x4, no-trans)
    const int lrow = (lane & 7) + 8 * ((lane >> 3) & 1);   // row within 16-row pair
    const int lcol = 8 * (lane >> 4);                      // col 0/8 select
    const int brow = (lane & 7) + 8 * (lane >> 4);         // B: row within 16, octet by bit4
    const int bcol = 8 * ((lane >> 3) & 1);

    // loop-invariant LDSM base addresses (bytes)
    const uint32_t aA   = sQ + (uint32_t)((mqw + lrow) * HST + lcol) * 2;           // A of S
    const uint32_t oB   =       (uint32_t)((nkw + brow) * HST + bcol) * 2;          // B of S (nb 0,1)
    const uint32_t oV   =       (uint32_t)(brow * VST + bcol) * 2;                  // B of PV (octets 0,1)

    const __half* WnB  = g_Whn + (size_t)b * N_ * DOUT;
    const __half* WtB  = g_WhT + (size_t)b * DOUT * N_;
    const int*    adjB = adj   + (size_t)b * N_ * N_;

    // prologue group 0: Q tile + K/Vt tile 0
#pragma unroll
    for (int i = tid; i < TM * 16; i += 256) {
        int r = i >> 4, ho = (i & 15) * 8;
        CP_ASYNC16(sQ + (r * HST + ho) * 2, WnB + (size_t)(q0 + r) * DOUT + ho);
        CP_ASYNC16(sK + (r * HST + ho) * 2, WnB + (size_t)r * DOUT + ho);
    }
#pragma unroll
    for (int i = tid; i < DOUT * 8; i += 256) {
        int r = i >> 3, co = (i & 7) * 8;
        CP_ASYNC16(sV + (r * VST + co) * 2, WtB + (size_t)r * N_ + co);
    }
    CP_COMMIT();
    if (tid < TM) dn[tid] = 0.0f;

    bool zq[2];
    zq[0] = (q0 + mqw + qr)     < ROWZ;
    zq[1] = (q0 + mqw + 8 + qr) < ROWZ;
    const int* ap[2];
    ap[0] = adjB + (size_t)(q0 + mqw + qr)     * N_ + nkw + 2 * qc;
    ap[1] = adjB + (size_t)(q0 + mqw + 8 + qr) * N_ + nkw + 2 * qc;

    float oacc[16][4];   // partial O: 16q x 128d over this warp's keys
#pragma unroll
    for (int nb = 0; nb < 16; nb++)
#pragma unroll
        for (int c = 0; c < 4; c++) oacc[nb][c] = 0.0f;
    float rsum[2] = {0.f, 0.f};

    for (int it = 0; it < N_ / TN; it++) {
        const int m0  = it * TN;
        const int cur = it & 1;

        CP_WAIT0();          // my tile-it copies done
        __syncthreads();     // all copies visible; prev iter's reads of alt done

        // issue tile it+1 into the alternate buffer (hidden under this tile)
        if (it < N_ / TN - 1) {
            const int mn = m0 + TN, alt = cur ^ 1;
#pragma unroll
            for (int i = tid; i < TN * 16; i += 256) {
                int r = i >> 4, ho = (i & 15) * 8;
                CP_ASYNC16(sK + (alt * TN * HST + r * HST + ho) * 2,
                           WnB + (size_t)(mn + r) * DOUT + ho);
            }
#pragma unroll
            for (int i = tid; i < DOUT * 8; i += 256) {
                int r = i >> 3, co = (i & 7) * 8;
                CP_ASYNC16(sV + (alt * DOUT * VST + r * VST + co) * 2,
                           WtB + (size_t)r * N_ + mn + co);
            }
        }
        CP_COMMIT();

        // adjacency masks for this warp's 32 keys (consumed after S)
        unsigned msk = 0;
#pragma unroll
        for (int rp = 0; rp < 2; rp++)
#pragma unroll
            for (int nb = 0; nb < 4; nb++) {
                int2 v = *(const int2*)(ap[rp] + m0 + 8 * nb);
                msk |= (unsigned)(v.x > 0) << (rp * 8 + nb * 2);
                msk |= (unsigned)(v.y > 0) << (rp * 8 + nb * 2 + 1);
            }

        // ---- S = Qn.Kn^T  (warp: 16q x 32k, LDSM-fed) ----
        const uint32_t kB = sK + (uint32_t)(cur * TN * HST) * 2 + oB;
        float sacc[4][4];
#pragma unroll
        for (int nb = 0; nb < 4; nb++)
#pragma unroll
            for (int c = 0; c < 4; c++) sacc[nb][c] = 0.0f;

#pragma unroll
        for (int k0 = 0; k0 < DOUT; k0 += 16) {
            unsigned a[4], b0[4], b1[4];
            ldsm_x4(a[0],  a[1],  a[2],  a[3],  aA + k0 * 2);
            ldsm_x4(b0[0], b0[1], b0[2], b0[3], kB + k0 * 2);                      // nb 0,1
            ldsm_x4(b1[0], b1[1], b1[2], b1[3], kB + (16 * HST + k0) * 2);         // nb 2,3
            mma_f16(sacc[0], a, b0[0], b0[1]);
            mma_f16(sacc[1], a, b0[2], b0[3]);
            mma_f16(sacc[2], a, b1[0], b1[1]);
            mma_f16(sacc[3], a, b1[2], b1[3]);
        }

        // ---- mask + exp -> P packed in registers ----
        unsigned pfrag[4][2];
#pragma unroll
        for (int nb = 0; nb < 4; nb++) {
            unsigned ml = msk >> (nb * 2);
            unsigned mh = msk >> (8 + nb * 2);
            float p0 = (ml & 1u) ? __expf(zq[0] ? 0.f : sacc[nb][0]) : 0.f;
            float p1 = (ml & 2u) ? __expf(zq[0] ? 0.f : sacc[nb][1]) : 0.f;
            float p2 = (mh & 1u) ? __expf(zq[1] ? 0.f : sacc[nb][2]) : 0.f;
            float p3 = (mh & 2u) ? __expf(zq[1] ? 0.f : sacc[nb][3]) : 0.f;
            __half2 ha = __floats2half2_rn(p0, p1);
            __half2 hb = __floats2half2_rn(p2, p3);
            float2 fa = __half22float2(ha), fb = __half22float2(hb);
            rsum[0] += fa.x + fa.y;
            rsum[1] += fb.x + fb.y;
            pfrag[nb][0] = *(unsigned*)&ha;
            pfrag[nb][1] = *(unsigned*)&hb;
        }

        // ---- partial O += P.V (own 32 keys, all 128 d; A regs, B LDSM) ----
        const uint32_t vB = sV + (uint32_t)(cur * DOUT * VST) * 2 + oV + (uint32_t)nkw * 2;
#pragma unroll
        for (int kc = 0; kc < 2; kc++) {
            unsigned a[4];
            a[0] = pfrag[2 * kc][0];
            a[1] = pfrag[2 * kc][1];
            a[2] = pfrag[2 * kc + 1][0];
            a[3] = pfrag[2 * kc + 1][1];
#pragma unroll
            for (int nbb = 0; nbb < 16; nbb += 2) {
                unsigned bv[4];
                ldsm_x4(bv[0], bv[1], bv[2], bv[3],
                        vB + (uint32_t)(nbb * 8 * VST + kc * 16) * 2);
                mma_f16(oacc[nbb],     a, bv[0], bv[1]);
                mma_f16(oacc[nbb + 1], a, bv[2], bv[3]);
            }
        }
    }

    // denominators (each split adds its own keys' sums)
#pragma unroll
    for (int rp = 0; rp < 2; rp++) {
        float v = rsum[rp];
        v += __shfl_xor_sync(0xffffffffu, v, 1);
        v += __shfl_xor_sync(0xffffffffu, v, 2);
        if (qc == 0) atomicAdd(&dn[mqw + 8 * rp + qr], v);
    }
    __syncthreads();   // dn complete; K/V buffers dead -> Ox overlay safe

    // cross-split O combine: split 1 parks its partial in smem
    if (split == 1) {
#pragma unroll
        for (int nb = 0; nb < 16; nb++) {
            int col = 8 * nb + 2 * qc;
            *(float2*)&Ox[(mqw + qr)     * 132 + col] = make_float2(oacc[nb][0], oacc[nb][1]);
            *(float2*)&Ox[(mqw + 8 + qr) * 132 + col] = make_float2(oacc[nb][2], oacc[nb][3]);
        }
    }
    __syncthreads();

    // split 0: combine, divide, ELU, store all 128 d
    if (split == 0) {
        float i0 = 1.0f / fmaxf(dn[mqw + qr],     1e-30f);
        float i1 = 1.0f / fmaxf(dn[mqw + 8 + qr], 1e-30f);
        int r0 = q0 + mqw + qr;
#pragma unroll
        for (int nb = 0; nb < 16; nb++) {
            int col = 8 * nb + 2 * qc;
            float2 xa = *(const float2*)&Ox[(mqw + qr)     * 132 + col];
            float2 xb = *(const float2*)&Ox[(mqw + 8 + qr) * 132 + col];
            float v0 = (oacc[nb][0] + xa.x) * i0, v1 = (oacc[nb][1] + xa.y) * i0;
            float v2 = (oacc[nb][2] + xb.x) * i1, v3 = (oacc[nb][3] + xb.y) * i1;
            v0 = (v0 > 0.f) ? v0 : expm1f(v0);
            v1 = (v1 > 0.f) ? v1 : expm1f(v1);
            v2 = (v2 > 0.f) ? v2 : expm1f(v2);
            v3 = (v3 > 0.f) ? v3 : expm1f(v3);
            *(float2*)&out[((size_t)b * N_ + r0)     * DOUT + col] = make_float2(v0, v1);
            *(float2*)&out[((size_t)b * N_ + r0 + 8) * DOUT + col] = make_float2(v2, v3);
        }
    }
}

// ---------------------------------------------------------------------------
// Launch
// ---------------------------------------------------------------------------
extern "C" void kernel_launch(void* const* d_in, const int* in_sizes, int n_in,
                              void* d_out, int out_size) {
    const float* h       = (const float*)d_in[0];   // [8,2048,256] f32
    // d_in[1] = adj (unused by the reference math)
    const int*   adj_eye = (const int*)d_in[2];     // [8,2048,2048] i32
    const float* W       = (const float*)d_in[3];   // [256,128] f32
    float* out = (float*)d_out;                     // [8,2048,128] f32

    const int smem_bytes =
        (TM * HST + 2 * TN * HST + 2 * DOUT * VST) * 2 + TM * 4;   // 89,344 B
    cudaFuncSetAttribute(attn, cudaFuncAttributeMaxDynamicSharedMemorySize, smem_bytes);

    gemmW<<<(B_ * N_) / 128, 256>>>(h, W);
    attn<<<dim3(N_ / TM, B_), 256, smem_bytes>>>(adj_eye, out);
}